// round 12
// baseline (speedup 1.0000x reference)
#include <cuda_runtime.h>
#include <cuda_bf16.h>
#include <cstdint>

#define BB 8
#define NN 4096
#define MM 4096
#define DD 128

// ===================== device scratch (no allocations allowed) =====================
__device__ __nv_bfloat16 g_d0h[(size_t)BB * NN * DD];
__device__ __nv_bfloat16 g_d0l[(size_t)BB * NN * DD];
__device__ __nv_bfloat16 g_d1h[(size_t)BB * MM * DD];
__device__ __nv_bfloat16 g_d1l[(size_t)BB * MM * DD];
__device__ int g_m0raw[BB * NN];
__device__ int g_m1raw[BB * MM];
// per-tile top-2 partials: [global row (B*N)][32 m-tiles] and [global col (B*M)][32 n-tiles]
__device__ float4 g_rowpart[(size_t)BB * NN * 32];
__device__ float4 g_colpart[(size_t)BB * MM * 32];

// ===================== normalize + bf16 hi/lo split =====================
__global__ void norm_kernel(const float* __restrict__ in,
                            __nv_bfloat16* __restrict__ hi,
                            __nv_bfloat16* __restrict__ lo, int rows) {
    int row = blockIdx.x * (blockDim.x >> 5) + (threadIdx.x >> 5);
    if (row >= rows) return;
    int lane = threadIdx.x & 31;
    float4 v = ((const float4*)(in + (size_t)row * DD))[lane];
    float ss = v.x * v.x + v.y * v.y + v.z * v.z + v.w * v.w;
    #pragma unroll
    for (int o = 16; o > 0; o >>= 1) ss += __shfl_xor_sync(0xffffffffu, ss, o);
    float inv = 1.0f / fmaxf(sqrtf(ss), 1e-12f);
    float n0 = v.x * inv, n1 = v.y * inv, n2 = v.z * inv, n3 = v.w * inv;
    __nv_bfloat16 h0 = __float2bfloat16(n0), h1 = __float2bfloat16(n1);
    __nv_bfloat16 h2 = __float2bfloat16(n2), h3 = __float2bfloat16(n3);
    __nv_bfloat16 l0 = __float2bfloat16(n0 - __bfloat162float(h0));
    __nv_bfloat16 l1 = __float2bfloat16(n1 - __bfloat162float(h1));
    __nv_bfloat16 l2 = __float2bfloat16(n2 - __bfloat162float(h2));
    __nv_bfloat16 l3 = __float2bfloat16(n3 - __bfloat162float(h3));
    __nv_bfloat162* ph = (__nv_bfloat162*)(hi + (size_t)row * DD + lane * 4);
    __nv_bfloat162* pl = (__nv_bfloat162*)(lo + (size_t)row * DD + lane * 4);
    ph[0] = __nv_bfloat162(h0, h1); ph[1] = __nv_bfloat162(h2, h3);
    pl[0] = __nv_bfloat162(l0, l1); pl[1] = __nv_bfloat162(l2, l3);
}

// ===================== top-2 helpers (tie: lower index wins) =====================
__device__ __forceinline__ bool better(float va, int ia, float vb, int ib) {
    return (va > vb) || (va == vb && ia < ib);
}
__device__ __forceinline__ void t2_update(float v, int idx, float& v0, int& i0, float& v1, int& i1) {
    if (better(v, idx, v0, i0)) { v1 = v0; i1 = i0; v0 = v; i0 = idx; }
    else if (better(v, idx, v1, i1)) { v1 = v; i1 = idx; }
}
// full-warp butterfly merge of sorted top-2 pairs
__device__ __forceinline__ void t2_bfly(float& v0, int& i0, float& v1, int& i1) {
    #pragma unroll
    for (int o = 16; o > 0; o >>= 1) {
        float w0 = __shfl_xor_sync(0xffffffffu, v0, o);
        int   j0 = __shfl_xor_sync(0xffffffffu, i0, o);
        float w1 = __shfl_xor_sync(0xffffffffu, v1, o);
        int   j1 = __shfl_xor_sync(0xffffffffu, i1, o);
        if (better(w0, j0, v0, i0)) {
            if (better(v0, i0, w1, j1)) { v1 = v0; i1 = i0; }
            else                        { v1 = w1; i1 = j1; }
            v0 = w0; i0 = j0;
        } else if (better(w0, j0, v1, i1)) { v1 = w0; i1 = j0; }
    }
}
__device__ __forceinline__ int ratio_test(float v0, int i0, float v1) {
    float d0 = 2.0f * (1.0f - v0);
    float d1 = 2.0f * (1.0f - v1);
    bool ok = (d0 <= 0.64f * d1) && (d0 <= 0.49f);
    return ok ? i0 : -1;
}

// ===================== warp-MMA GEMM + fused partial top-2 =====================
// Tile: 128x128x128 per CTA, 512 threads = 4x4 warps, 32x32 per warp.

#define SM_AH 0
#define SM_AL 32768
#define SM_BH 65536
#define SM_BL 98304
#define SM_TOTAL 131072
#define SPITCH 129   // stage pitch: 129 % 32 == 1 -> conflict-free column reads

__device__ __forceinline__ uint32_t smem_u32(const void* p) {
    uint32_t a;
    asm("{ .reg .u64 t; cvta.to.shared.u64 t, %1; cvt.u32.u64 %0, t; }" : "=r"(a) : "l"(p));
    return a;
}

#define LDSM_X4(r, a) \
    asm volatile("ldmatrix.sync.aligned.m8n8.x4.shared.b16 {%0,%1,%2,%3}, [%4];" \
        : "=r"((r)[0]), "=r"((r)[1]), "=r"((r)[2]), "=r"((r)[3]) : "r"(a))

#define MMA16816(acc, a, b0_, b1_) \
    asm volatile("mma.sync.aligned.m16n8k16.row.col.f32.bf16.bf16.f32 " \
        "{%0,%1,%2,%3},{%4,%5,%6,%7},{%8,%9},{%0,%1,%2,%3};" \
        : "+f"((acc)[0]), "+f"((acc)[1]), "+f"((acc)[2]), "+f"((acc)[3]) \
        : "r"((a)[0]), "r"((a)[1]), "r"((a)[2]), "r"((a)[3]), "r"(b0_), "r"(b1_))

__global__ void __launch_bounds__(512, 1)
gemm_mma_kernel(float* __restrict__ sim) {
    extern __shared__ char smem[];
    const uint32_t sb = smem_u32(smem);

    const int b  = blockIdx.z;
    const int nt = blockIdx.y;         // n-tile index (0..31)
    const int mt = blockIdx.x;         // m-tile index (0..31)
    const int n0 = nt * 128;
    const int m0 = mt * 128;
    const int tid  = threadIdx.x;
    const int wid  = tid >> 5, lane = tid & 31;
    const int wm   = wid >> 2;
    const int wn   = wid & 3;

    // ---- cooperative load: 4 contiguous 32KB tiles, swizzled [row*256 + (ch^(row&7))*16]
    {
        const uint4* a_h = (const uint4*)(g_d0h + ((size_t)b * NN + n0) * DD);
        const uint4* a_l = (const uint4*)(g_d0l + ((size_t)b * NN + n0) * DD);
        const uint4* b_h = (const uint4*)(g_d1h + ((size_t)b * MM + m0) * DD);
        const uint4* b_l = (const uint4*)(g_d1l + ((size_t)b * MM + m0) * DD);
        #pragma unroll
        for (int i = tid; i < 2048; i += 512) {
            int row = i >> 4, ch = i & 15;
            uint32_t soff = (uint32_t)(row * 256 + ((ch ^ (row & 7)) << 4));
            *(uint4*)(smem + SM_AH + soff) = __ldg(a_h + i);
            *(uint4*)(smem + SM_AL + soff) = __ldg(a_l + i);
            *(uint4*)(smem + SM_BH + soff) = __ldg(b_h + i);
            *(uint4*)(smem + SM_BL + soff) = __ldg(b_l + i);
        }
    }
    __syncthreads();

    const int a_row = wm * 32 + (lane & 15);
    const int a_cof = (lane >> 4) & 1;
    const int b_row = wn * 32 + (lane & 7) + ((lane >> 4) << 3);
    const int b_cof = (lane >> 3) & 1;

    float acc[2][4][4];
    #pragma unroll
    for (int tm = 0; tm < 2; tm++)
        #pragma unroll
        for (int j = 0; j < 4; j++)
            #pragma unroll
            for (int q = 0; q < 4; q++) acc[tm][j][q] = 0.f;

    #pragma unroll
    for (int ks = 0; ks < 8; ks++) {
        uint32_t ah[2][4], al[2][4], bh[2][4], bl[2][4];
        #pragma unroll
        for (int tm = 0; tm < 2; tm++) {
            int row = a_row + tm * 16;
            uint32_t addr = (uint32_t)(row * 256 + (((2 * ks + a_cof) ^ (row & 7)) << 4));
            LDSM_X4(ah[tm], sb + SM_AH + addr);
            LDSM_X4(al[tm], sb + SM_AL + addr);
        }
        #pragma unroll
        for (int tb = 0; tb < 2; tb++) {
            int row = b_row + tb * 16;
            uint32_t addr = (uint32_t)(row * 256 + (((2 * ks + b_cof) ^ (row & 7)) << 4));
            LDSM_X4(bh[tb], sb + SM_BH + addr);
            LDSM_X4(bl[tb], sb + SM_BL + addr);
        }
        #pragma unroll
        for (int tm = 0; tm < 2; tm++)
            #pragma unroll
            for (int j = 0; j < 4; j++) {
                int tb = j >> 1, s = (j & 1) * 2;
                MMA16816(acc[tm][j], ah[tm], bh[tb][s], bh[tb][s + 1]);  // hi*hi
                MMA16816(acc[tm][j], ah[tm], bl[tb][s], bl[tb][s + 1]);  // hi*lo
                MMA16816(acc[tm][j], al[tm], bh[tb][s], bh[tb][s + 1]);  // lo*hi
            }
    }

    // ---- write sim (float2, coalesced)
    const int g = lane >> 2, c2 = (lane & 3) * 2;
    #pragma unroll
    for (int tm = 0; tm < 2; tm++) {
        #pragma unroll
        for (int j = 0; j < 4; j++) {
            size_t row0 = (size_t)b * NN + n0 + wm * 32 + tm * 16 + g;
            int col = m0 + wn * 32 + j * 8 + c2;
            *(float2*)(sim + row0 * MM + col)       = make_float2(acc[tm][j][0], acc[tm][j][1]);
            *(float2*)(sim + (row0 + 8) * MM + col) = make_float2(acc[tm][j][2], acc[tm][j][3]);
        }
    }

    // ---- stage tile into smem (tiles are dead now) and do per-tile top-2
    __syncthreads();
    float* S = (float*)smem;
    #pragma unroll
    for (int tm = 0; tm < 2; tm++) {
        #pragma unroll
        for (int j = 0; j < 4; j++) {
            int r  = wm * 32 + tm * 16 + g;
            int cc = wn * 32 + j * 8 + c2;
            S[r * SPITCH + cc]           = acc[tm][j][0];
            S[r * SPITCH + cc + 1]       = acc[tm][j][1];
            S[(r + 8) * SPITCH + cc]     = acc[tm][j][2];
            S[(r + 8) * SPITCH + cc + 1] = acc[tm][j][3];
        }
    }
    __syncthreads();

    // row top-2: warp handles rows wid*8 .. wid*8+7 (global col indices)
    #pragma unroll
    for (int rr = 0; rr < 8; rr++) {
        int r = wid * 8 + rr;
        float v0 = -2.f, v1 = -2.f; int i0 = -1, i1 = -1;
        #pragma unroll
        for (int k = 0; k < 4; k++) {
            int cc = lane * 4 + k;
            t2_update(S[r * SPITCH + cc], m0 + cc, v0, i0, v1, i1);
        }
        t2_bfly(v0, i0, v1, i1);
        if (lane == 0)
            g_rowpart[((size_t)(b * 32 + nt) * 128 + r) * 32 + mt] =
                make_float4(v0, __int_as_float(i0), v1, __int_as_float(i1));
    }

    // col top-2: warp handles cols wid*8 .. wid*8+7 (global row indices)
    #pragma unroll
    for (int cc8 = 0; cc8 < 8; cc8++) {
        int cc = wid * 8 + cc8;
        float v0 = -2.f, v1 = -2.f; int i0 = -1, i1 = -1;
        #pragma unroll
        for (int k = 0; k < 4; k++) {
            int r = lane + 32 * k;
            t2_update(S[r * SPITCH + cc], n0 + r, v0, i0, v1, i1);
        }
        t2_bfly(v0, i0, v1, i1);
        if (lane == 0)
            g_colpart[((size_t)(b * 32 + mt) * 128 + cc) * 32 + nt] =
                make_float4(v0, __int_as_float(i0), v1, __int_as_float(i1));
    }
}

// ===================== partial reductions: one warp per row/col =====================
__global__ void reduce_row_kernel() {
    int row = blockIdx.x * (blockDim.x >> 5) + (threadIdx.x >> 5);   // 0..B*N-1
    int lane = threadIdx.x & 31;
    float4 p = g_rowpart[(size_t)row * 32 + lane];
    float v0 = p.x, v1 = p.z;
    int i0 = __float_as_int(p.y), i1 = __float_as_int(p.w);
    t2_bfly(v0, i0, v1, i1);
    if (lane == 0) g_m0raw[row] = ratio_test(v0, i0, v1);
}
__global__ void reduce_col_kernel() {
    int col = blockIdx.x * (blockDim.x >> 5) + (threadIdx.x >> 5);   // 0..B*M-1
    int lane = threadIdx.x & 31;
    float4 p = g_colpart[(size_t)col * 32 + lane];
    float v0 = p.x, v1 = p.z;
    int i0 = __float_as_int(p.y), i1 = __float_as_int(p.w);
    t2_bfly(v0, i0, v1, i1);
    if (lane == 0) g_m1raw[col] = ratio_test(v0, i0, v1);
}

// ---------------- mutual check + small outputs ----------------
__global__ void mutual_kernel(float* __restrict__ out) {
    int i = blockIdx.x * blockDim.x + threadIdx.x;
    if (i >= BB * NN) return;
    int b = i >> 12, n = i & 4095;
    int a = g_m0raw[i];
    int r0 = (a > -1 && g_m1raw[(b << 12) + a] == n) ? a : -1;
    int c = g_m1raw[i];
    int r1 = (c > -1 && g_m0raw[(b << 12) + c] == n) ? c : -1;
    const int BN = BB * NN;
    out[i]          = (float)r0;
    out[BN + i]     = (float)r1;
    out[2 * BN + i] = (r0 > -1) ? 1.0f : 0.0f;
    out[3 * BN + i] = (r1 > -1) ? 1.0f : 0.0f;
}

// ===================== launch =====================
extern "C" void kernel_launch(void* const* d_in, const int* in_sizes, int n_in,
                              void* d_out, int out_size) {
    const float* desc0 = (const float*)d_in[0];
    const float* desc1 = (const float*)d_in[1];
    float* out = (float*)d_out;
    float* sim = out + 4 * BB * NN;

    __nv_bfloat16 *d0h, *d0l, *d1h, *d1l;
    cudaGetSymbolAddress((void**)&d0h, g_d0h);
    cudaGetSymbolAddress((void**)&d0l, g_d0l);
    cudaGetSymbolAddress((void**)&d1h, g_d1h);
    cudaGetSymbolAddress((void**)&d1l, g_d1l);

    cudaFuncSetAttribute(gemm_mma_kernel, cudaFuncAttributeMaxDynamicSharedMemorySize, SM_TOTAL);

    norm_kernel<<<(BB * NN) / 8, 256>>>(desc0, d0h, d0l, BB * NN);
    norm_kernel<<<(BB * MM) / 8, 256>>>(desc1, d1h, d1l, BB * MM);

    dim3 ggrid(MM / 128, NN / 128, BB);
    gemm_mma_kernel<<<ggrid, 512, SM_TOTAL>>>(sim);

    reduce_row_kernel<<<(BB * NN) / 8, 256>>>();
    reduce_col_kernel<<<(BB * MM) / 8, 256>>>();

    mutual_kernel<<<(BB * NN + 255) / 256, 256>>>(out);
}

// round 15
// speedup vs baseline: 1.8113x; 1.8113x over previous
#include <cuda_runtime.h>
#include <cuda_bf16.h>
#include <cstdint>

#define BB 8
#define NN 4096
#define MM 4096
#define DD 128

// ===================== device scratch (no allocations allowed) =====================
__device__ __nv_bfloat16 g_d0h[(size_t)BB * NN * DD];
__device__ __nv_bfloat16 g_d0l[(size_t)BB * NN * DD];
__device__ __nv_bfloat16 g_d1h[(size_t)BB * MM * DD];
__device__ __nv_bfloat16 g_d1l[(size_t)BB * MM * DD];
__device__ int g_m0raw[BB * NN];
__device__ int g_m1raw[BB * MM];
// per-tile top-2 partials: [global row (B*N)][32 m-tiles] and [global col (B*M)][32 n-tiles]
__device__ float4 g_rowpart[(size_t)BB * NN * 32];
__device__ float4 g_colpart[(size_t)BB * MM * 32];

// ===================== normalize + bf16 hi/lo split =====================
__global__ void norm_kernel(const float* __restrict__ in,
                            __nv_bfloat16* __restrict__ hi,
                            __nv_bfloat16* __restrict__ lo, int rows) {
    int row = blockIdx.x * (blockDim.x >> 5) + (threadIdx.x >> 5);
    if (row >= rows) return;
    int lane = threadIdx.x & 31;
    float4 v = ((const float4*)(in + (size_t)row * DD))[lane];
    float ss = v.x * v.x + v.y * v.y + v.z * v.z + v.w * v.w;
    #pragma unroll
    for (int o = 16; o > 0; o >>= 1) ss += __shfl_xor_sync(0xffffffffu, ss, o);
    float inv = 1.0f / fmaxf(sqrtf(ss), 1e-12f);
    float n0 = v.x * inv, n1 = v.y * inv, n2 = v.z * inv, n3 = v.w * inv;
    __nv_bfloat16 h0 = __float2bfloat16(n0), h1 = __float2bfloat16(n1);
    __nv_bfloat16 h2 = __float2bfloat16(n2), h3 = __float2bfloat16(n3);
    __nv_bfloat16 l0 = __float2bfloat16(n0 - __bfloat162float(h0));
    __nv_bfloat16 l1 = __float2bfloat16(n1 - __bfloat162float(h1));
    __nv_bfloat16 l2 = __float2bfloat16(n2 - __bfloat162float(h2));
    __nv_bfloat16 l3 = __float2bfloat16(n3 - __bfloat162float(h3));
    __nv_bfloat162* ph = (__nv_bfloat162*)(hi + (size_t)row * DD + lane * 4);
    __nv_bfloat162* pl = (__nv_bfloat162*)(lo + (size_t)row * DD + lane * 4);
    ph[0] = __nv_bfloat162(h0, h1); ph[1] = __nv_bfloat162(h2, h3);
    pl[0] = __nv_bfloat162(l0, l1); pl[1] = __nv_bfloat162(l2, l3);
}

// ===================== helpers =====================
__device__ __forceinline__ uint32_t smem_u32(const void* p) {
    uint32_t a;
    asm("{ .reg .u64 t; cvta.to.shared.u64 t, %1; cvt.u32.u64 %0, t; }" : "=r"(a) : "l"(p));
    return a;
}
__device__ __forceinline__ void cp16(uint32_t saddr, const void* g) {
    asm volatile("cp.async.cg.shared.global [%0], [%1], 16;" :: "r"(saddr), "l"(g));
}

#define LDSM_X4(r, a) \
    asm volatile("ldmatrix.sync.aligned.m8n8.x4.shared.b16 {%0,%1,%2,%3}, [%4];" \
        : "=r"((r)[0]), "=r"((r)[1]), "=r"((r)[2]), "=r"((r)[3]) : "r"(a))

#define MMA16816(acc, a, b0_, b1_) \
    asm volatile("mma.sync.aligned.m16n8k16.row.col.f32.bf16.bf16.f32 " \
        "{%0,%1,%2,%3},{%4,%5,%6,%7},{%8,%9},{%0,%1,%2,%3};" \
        : "+f"((acc)[0]), "+f"((acc)[1]), "+f"((acc)[2]), "+f"((acc)[3]) \
        : "r"((a)[0]), "r"((a)[1]), "r"((a)[2]), "r"((a)[3]), "r"(b0_), "r"(b1_))

// ===================== pipelined warp-MMA GEMM =====================
// CTA: 64-row A panel resident, streams 32 B tiles (128 rows each) with cp.async
// double buffering. 256 threads = 8 warps (2x4), warp tile 32x32, 3-pass hi/lo bf16.
#define SMA_H 0
#define SMA_L 16384
#define SMB_BASE 32768
#define SMB_SZ 65536              // per buffer: Bh 32KB + Bl 32KB
#define SM_TOTAL_G (SMB_BASE + 2 * SMB_SZ)   // 160 KB

__global__ void __launch_bounds__(256, 1)
gemm_pipe_kernel(float* __restrict__ sim) {
    extern __shared__ char smem[];
    const uint32_t sb = smem_u32(smem);

    const int x = blockIdx.x;
    const int b = x >> 6, np = x & 63;
    const int n0 = np << 6;                    // 64-row A panel
    const int tid = threadIdx.x;
    const int wid = tid >> 5, lane = tid & 31;
    const int wm = wid >> 2, wn = wid & 3;

    const char* a_h = (const char*)(g_d0h + ((size_t)b * NN + n0) * DD);
    const char* a_l = (const char*)(g_d0l + ((size_t)b * NN + n0) * DD);
    const char* b_h = (const char*)(g_d1h + (size_t)b * MM * DD);
    const char* b_l = (const char*)(g_d1l + (size_t)b * MM * DD);

    // prologue: A panel (64x16 chunks) + B tile 0 (128x16 chunks), one cp.async group
    #pragma unroll
    for (int i = tid; i < 1024; i += 256) {
        int row = i >> 4, ch = i & 15;
        uint32_t soff = (uint32_t)(row * 256 + ((ch ^ (row & 7)) << 4));
        cp16(sb + SMA_H + soff, a_h + (size_t)i * 16);
        cp16(sb + SMA_L + soff, a_l + (size_t)i * 16);
    }
    #pragma unroll
    for (int i = tid; i < 2048; i += 256) {
        int row = i >> 4, ch = i & 15;
        uint32_t soff = (uint32_t)(row * 256 + ((ch ^ (row & 7)) << 4));
        cp16(sb + SMB_BASE + soff, b_h + (size_t)i * 16);
        cp16(sb + SMB_BASE + 32768 + soff, b_l + (size_t)i * 16);
    }
    asm volatile("cp.async.commit_group;" ::: "memory");

    const int a_row = wm * 32 + (lane & 15);
    const int a_cof = (lane >> 4) & 1;
    const int b_row = wn * 32 + (lane & 7) + ((lane >> 4) << 3);
    const int b_cof = (lane >> 3) & 1;
    const int g = lane >> 2, c2 = (lane & 3) * 2;

    for (int mt = 0; mt < 32; mt++) {
        // prefetch next B tile into the other buffer
        if (mt < 31) {
            uint32_t nbuf = sb + SMB_BASE + (uint32_t)((mt + 1) & 1) * SMB_SZ;
            const char* nbh = b_h + (size_t)(mt + 1) * 128 * 256;
            const char* nbl = b_l + (size_t)(mt + 1) * 128 * 256;
            #pragma unroll
            for (int i = tid; i < 2048; i += 256) {
                int row = i >> 4, ch = i & 15;
                uint32_t soff = (uint32_t)(row * 256 + ((ch ^ (row & 7)) << 4));
                cp16(nbuf + soff, nbh + (size_t)i * 16);
                cp16(nbuf + 32768 + soff, nbl + (size_t)i * 16);
            }
            asm volatile("cp.async.commit_group;" ::: "memory");
            asm volatile("cp.async.wait_group 1;" ::: "memory");
        } else {
            asm volatile("cp.async.wait_group 0;" ::: "memory");
        }
        __syncthreads();

        const uint32_t cbh = sb + SMB_BASE + (uint32_t)(mt & 1) * SMB_SZ;
        const uint32_t cbl = cbh + 32768;

        float acc[2][4][4];
        #pragma unroll
        for (int tm = 0; tm < 2; tm++)
            #pragma unroll
            for (int j = 0; j < 4; j++)
                #pragma unroll
                for (int q = 0; q < 4; q++) acc[tm][j][q] = 0.f;

        #pragma unroll
        for (int ks = 0; ks < 8; ks++) {
            uint32_t ah[2][4], al[2][4], bh[2][4], bl[2][4];
            #pragma unroll
            for (int tm = 0; tm < 2; tm++) {
                int row = a_row + tm * 16;
                uint32_t addr = (uint32_t)(row * 256 + (((2 * ks + a_cof) ^ (row & 7)) << 4));
                LDSM_X4(ah[tm], sb + SMA_H + addr);
                LDSM_X4(al[tm], sb + SMA_L + addr);
            }
            #pragma unroll
            for (int tb = 0; tb < 2; tb++) {
                int row = b_row + tb * 16;
                uint32_t addr = (uint32_t)(row * 256 + (((2 * ks + b_cof) ^ (row & 7)) << 4));
                LDSM_X4(bh[tb], cbh + addr);
                LDSM_X4(bl[tb], cbl + addr);
            }
            #pragma unroll
            for (int tm = 0; tm < 2; tm++)
                #pragma unroll
                for (int j = 0; j < 4; j++) {
                    int tb = j >> 1, s = (j & 1) * 2;
                    MMA16816(acc[tm][j], ah[tm], bh[tb][s], bh[tb][s + 1]);  // hi*hi
                    MMA16816(acc[tm][j], ah[tm], bl[tb][s], bl[tb][s + 1]);  // hi*lo
                    MMA16816(acc[tm][j], al[tm], bh[tb][s], bh[tb][s + 1]);  // lo*hi
                }
        }

        // write sim slice (float2 coalesced)
        #pragma unroll
        for (int tm = 0; tm < 2; tm++) {
            #pragma unroll
            for (int j = 0; j < 4; j++) {
                size_t row0 = (size_t)b * NN + n0 + wm * 32 + tm * 16 + g;
                int col = mt * 128 + wn * 32 + j * 8 + c2;
                *(float2*)(sim + row0 * MM + col)       = make_float2(acc[tm][j][0], acc[tm][j][1]);
                *(float2*)(sim + (row0 + 8) * MM + col) = make_float2(acc[tm][j][2], acc[tm][j][3]);
            }
        }
        __syncthreads();   // protect current buffer before next iteration's prefetch reuses it
    }
}

// ===================== single-pass tile top-2 (rows + cols, no shuffles) =====================
#define TP 129   // smem pitch: conflict-free for both row and column scans

__global__ void __launch_bounds__(256)
top2_tile_kernel(const float* __restrict__ sim) {
    extern __shared__ float S[];   // 128 * 129 floats = 66048 B
    const int mt = blockIdx.x, nt = blockIdx.y, b = blockIdx.z;
    const int m0 = mt << 7, n0 = nt << 7;
    const int tid = threadIdx.x;

    const float* base = sim + ((size_t)b * NN + n0) * MM + m0;
    #pragma unroll
    for (int i = tid; i < 128 * 32; i += 256) {
        int r = i >> 5, c4 = (i & 31) * 4;
        float4 v = __ldg((const float4*)(base + (size_t)r * MM + c4));
        float* d = S + r * TP + c4;
        d[0] = v.x; d[1] = v.y; d[2] = v.z; d[3] = v.w;
    }
    __syncthreads();

    if (tid < 128) {
        // row scan: strict '>' with ascending col preserves lower-index tie rule
        int r = tid;
        const float* p = S + r * TP;
        float v0 = -2.f, v1 = -2.f; int i0 = -1, i1 = -1;
        #pragma unroll 8
        for (int c = 0; c < 128; c++) {
            float v = p[c];
            if (v > v0)      { v1 = v0; i1 = i0; v0 = v; i0 = m0 + c; }
            else if (v > v1) { v1 = v; i1 = m0 + c; }
        }
        g_rowpart[((size_t)(b * 32 + nt) * 128 + r) * 32 + mt] =
            make_float4(v0, __int_as_float(i0), v1, __int_as_float(i1));
    } else {
        // column scan
        int c = tid - 128;
        float v0 = -2.f, v1 = -2.f; int i0 = -1, i1 = -1;
        #pragma unroll 8
        for (int r = 0; r < 128; r++) {
            float v = S[r * TP + c];
            if (v > v0)      { v1 = v0; i1 = i0; v0 = v; i0 = n0 + r; }
            else if (v > v1) { v1 = v; i1 = n0 + r; }
        }
        g_colpart[((size_t)(b * 32 + mt) * 128 + c) * 32 + nt] =
            make_float4(v0, __int_as_float(i0), v1, __int_as_float(i1));
    }
}

// ===================== merge helpers + reductions =====================
__device__ __forceinline__ bool better(float va, int ia, float vb, int ib) {
    return (va > vb) || (va == vb && ia < ib);
}
__device__ __forceinline__ void t2_bfly(float& v0, int& i0, float& v1, int& i1) {
    #pragma unroll
    for (int o = 16; o > 0; o >>= 1) {
        float w0 = __shfl_xor_sync(0xffffffffu, v0, o);
        int   j0 = __shfl_xor_sync(0xffffffffu, i0, o);
        float w1 = __shfl_xor_sync(0xffffffffu, v1, o);
        int   j1 = __shfl_xor_sync(0xffffffffu, i1, o);
        if (better(w0, j0, v0, i0)) {
            if (better(v0, i0, w1, j1)) { v1 = v0; i1 = i0; }
            else                        { v1 = w1; i1 = j1; }
            v0 = w0; i0 = j0;
        } else if (better(w0, j0, v1, i1)) { v1 = w0; i1 = j0; }
    }
}
__device__ __forceinline__ int ratio_test(float v0, int i0, float v1) {
    float d0 = 2.0f * (1.0f - v0);
    float d1 = 2.0f * (1.0f - v1);
    bool ok = (d0 <= 0.64f * d1) && (d0 <= 0.49f);
    return ok ? i0 : -1;
}

__global__ void reduce_row_kernel() {
    int row = blockIdx.x * (blockDim.x >> 5) + (threadIdx.x >> 5);
    int lane = threadIdx.x & 31;
    float4 p = g_rowpart[(size_t)row * 32 + lane];
    float v0 = p.x, v1 = p.z;
    int i0 = __float_as_int(p.y), i1 = __float_as_int(p.w);
    t2_bfly(v0, i0, v1, i1);
    if (lane == 0) g_m0raw[row] = ratio_test(v0, i0, v1);
}
__global__ void reduce_col_kernel() {
    int col = blockIdx.x * (blockDim.x >> 5) + (threadIdx.x >> 5);
    int lane = threadIdx.x & 31;
    float4 p = g_colpart[(size_t)col * 32 + lane];
    float v0 = p.x, v1 = p.z;
    int i0 = __float_as_int(p.y), i1 = __float_as_int(p.w);
    t2_bfly(v0, i0, v1, i1);
    if (lane == 0) g_m1raw[col] = ratio_test(v0, i0, v1);
}

// ---------------- mutual check + small outputs ----------------
__global__ void mutual_kernel(float* __restrict__ out) {
    int i = blockIdx.x * blockDim.x + threadIdx.x;
    if (i >= BB * NN) return;
    int b = i >> 12, n = i & 4095;
    int a = g_m0raw[i];
    int r0 = (a > -1 && g_m1raw[(b << 12) + a] == n) ? a : -1;
    int c = g_m1raw[i];
    int r1 = (c > -1 && g_m0raw[(b << 12) + c] == n) ? c : -1;
    const int BN = BB * NN;
    out[i]          = (float)r0;
    out[BN + i]     = (float)r1;
    out[2 * BN + i] = (r0 > -1) ? 1.0f : 0.0f;
    out[3 * BN + i] = (r1 > -1) ? 1.0f : 0.0f;
}

// ===================== launch =====================
extern "C" void kernel_launch(void* const* d_in, const int* in_sizes, int n_in,
                              void* d_out, int out_size) {
    const float* desc0 = (const float*)d_in[0];
    const float* desc1 = (const float*)d_in[1];
    float* out = (float*)d_out;
    float* sim = out + 4 * BB * NN;

    __nv_bfloat16 *d0h, *d0l, *d1h, *d1l;
    cudaGetSymbolAddress((void**)&d0h, g_d0h);
    cudaGetSymbolAddress((void**)&d0l, g_d0l);
    cudaGetSymbolAddress((void**)&d1h, g_d1h);
    cudaGetSymbolAddress((void**)&d1l, g_d1l);

    cudaFuncSetAttribute(gemm_pipe_kernel, cudaFuncAttributeMaxDynamicSharedMemorySize, SM_TOTAL_G);
    cudaFuncSetAttribute(top2_tile_kernel, cudaFuncAttributeMaxDynamicSharedMemorySize, 128 * TP * 4);

    norm_kernel<<<(BB * NN) / 8, 256>>>(desc0, d0h, d0l, BB * NN);
    norm_kernel<<<(BB * MM) / 8, 256>>>(desc1, d1h, d1l, BB * MM);

    gemm_pipe_kernel<<<BB * 64, 256, SM_TOTAL_G>>>(sim);

    dim3 tgrid(MM / 128, NN / 128, BB);
    top2_tile_kernel<<<tgrid, 256, 128 * TP * 4>>>(sim);

    reduce_row_kernel<<<(BB * NN) / 8, 256>>>();
    reduce_col_kernel<<<(BB * MM) / 8, 256>>>();

    mutual_kernel<<<(BB * NN + 255) / 256, 256>>>(out);
}